// round 17
// baseline (speedup 1.0000x reference)
#include <cuda_runtime.h>
#include <math_constants.h>
#include <stdint.h>

#define KCODES 512
#define DDIM   64
#define QELEMS 4194304
#define NBLK   148
#define NTHR   256
#define RPAD   68             // padded row stride (floats); 272 B, 16B-aligned
#define NTILES 4096           // 65536 / 16 rows per tile

__device__ double   g_partial[NBLK];
__device__ unsigned g_count = 0;

// ---- smem float offsets ----
#define OFF_SW    0                        // [512][68] codebook
#define OFF_SB    (512 * RPAD)             // [512] code norms        34816
#define OFF_SX    (OFF_SB + 512)           // [8][16][68] x tiles     35328
#define OFF_SA    (OFF_SX + 8 * 16 * RPAD) // [8][16] row norms       44032
#define OFF_WIN   (OFF_SA + 128)           // [8][16] winners         44160
#define OFF_SRED  (OFF_WIN + 128)          // [256] double  (44288*4 % 8 == 0)
#define SMEM_BYTES ((OFF_SRED + 512) * 4)  // 179200 B

// ---------------------------------------------------------------------------
// Zero this block's encoding rows; enc base is only 4B-aligned
// (d_out+4+4*QELEMS) -> scalar fringes around a float4 interior.
// ---------------------------------------------------------------------------
__device__ __forceinline__ void zero_rows(float* __restrict__ enc,
                                          int row0, int nrows, int tid) {
    float* p = enc + (size_t)row0 * KCODES;
    int n = nrows * KCODES;
    uintptr_t a = (uintptr_t)p;
    int head = (int)((((a + 15) & ~(uintptr_t)15) - a) >> 2);   // 0..3
    if (tid < head) p[tid] = 0.0f;
    int n4 = (n - head) >> 2;
    int tail = (n - head) & 3;
    float4* v = (float4*)(p + head);
    float4 z = make_float4(0.f, 0.f, 0.f, 0.f);
    #pragma unroll 4
    for (int i = tid; i < n4; i += NTHR) v[i] = z;
    if (tid >= 4 && tid - 4 < tail) p[head + 4 * n4 + (tid - 4)] = 0.0f;
}

// ---------------------------------------------------------------------------
// 4x4 register-blocked kernel. Warp tile = 16 rows x 32 codes per pass.
// lane = (lr = lane>>3, lc = lane&7): rows lr*4+i, codes kb + lc + 8j.
// Per d-chunk (4): 8 LDS.128 + 64 FFMA per lane; accumulation ascending-d
// per (row,code) == reference rounding chain.
// ---------------------------------------------------------------------------
__global__ void __launch_bounds__(NTHR, 1) vq_fused(
    const float* __restrict__ x,
    const float* __restrict__ w,
    float* __restrict__ out,       // out[0] = loss
    float* __restrict__ qout,
    float* __restrict__ enc)
{
    extern __shared__ float sm[];
    float*  sw   = sm + OFF_SW;                // [512][68]
    float*  sb   = sm + OFF_SB;                // [512]
    float*  sx   = sm + OFF_SX;                // [8][16][68]
    float*  sa   = sm + OFF_SA;                // [8][16]
    int*    swin = (int*)(sm + OFF_WIN);       // [8][16]
    double* sred = (double*)(sm + OFF_SRED);   // [256]

    const int tid  = threadIdx.x;
    const int bid  = blockIdx.x;
    const int wid  = tid >> 5;
    const int lane = tid & 31;
    const int lr   = lane >> 3;     // row group 0..3
    const int lc   = lane & 7;      // code group 0..7

    // Tiles: 100 blocks x 28, 48 blocks x 27  (100*28 + 48*27 = 4096)
    const int cnt = (bid < 100) ? 28 : 27;
    const int t0  = (bid < 100) ? bid * 28 : 2800 + (bid - 100) * 27;

    // Stage codebook into padded smem (coalesced LDG)
    #pragma unroll 4
    for (int i = tid; i < KCODES * DDIM; i += NTHR)
        sw[(i >> 6) * RPAD + (i & 63)] = w[i];

    // Zero-fill exactly this block's enc rows (drains under the FFMA loop)
    zero_rows(enc, t0 * 16, cnt * 16, tid);
    __syncthreads();

    // Codebook norms — identical rounding chain to reference
    #pragma unroll 1
    for (int k = tid; k < KCODES; k += NTHR) {
        const float* pk = sw + k * RPAD;
        float acc = 0.0f;
        #pragma unroll 8
        for (int d = 0; d < DDIM; d++)
            acc = __fadd_rn(acc, __fmul_rn(pk[d], pk[d]));
        sb[k] = acc;
    }
    __syncthreads();

    float* sxw  = sx + wid * 16 * RPAD;
    float* saw  = sa + wid * 16;
    int*   winw = swin + wid * 16;
    double ls = 0.0;

    #pragma unroll 1
    for (int i8 = 0; i8 < 4; i8++) {
        const int lt = wid + 8 * i8;
        if (lt >= cnt) break;
        const int row0 = (t0 + lt) * 16;

        // ---- Stage x tile (warp-local; coalesced LDG) --------------------
        #pragma unroll 4
        for (int it = 0; it < 32; it++) {
            int idx = lane + 32 * it;
            int r = idx & 15, d = idx >> 4;
            int n = row0 + r, b = n >> 10, hw = n & 1023;
            sxw[r * RPAD + d] = x[(size_t)b * 65536 + hw + (size_t)d * 1024];
        }
        __syncwarp();

        // Row norms (sequential reference chain)
        if (lane < 16) {
            const float* pr = sxw + lane * RPAD;
            float acc = 0.0f;
            #pragma unroll 8
            for (int d = 0; d < DDIM; d++)
                acc = __fadd_rn(acc, __fmul_rn(pr[d], pr[d]));
            saw[lane] = acc;
        }
        __syncwarp();

        float av[4];
        #pragma unroll
        for (int i = 0; i < 4; i++) av[i] = saw[lr * 4 + i];

        float bd[4]; int bk[4];
        #pragma unroll
        for (int i = 0; i < 4; i++) { bd[i] = CUDART_INF_F; bk[i] = 0x7fffffff; }

        // ---- 16 passes x 32 codes: 4x4 register-blocked GEMM -------------
        #pragma unroll 1
        for (int pass = 0; pass < 16; pass++) {
            const int kb = pass * 32;
            const float* w0 = sw + (kb + lc) * RPAD;
            const float* x0 = sxw + (lr * 4) * RPAD;
            float acc[16];
            #pragma unroll
            for (int i = 0; i < 16; i++) acc[i] = 0.0f;

            #pragma unroll 2
            for (int c = 0; c < 16; c++) {
                float4 xv0 = *(const float4*)(x0 + 0 * RPAD + c * 4);
                float4 xv1 = *(const float4*)(x0 + 1 * RPAD + c * 4);
                float4 xv2 = *(const float4*)(x0 + 2 * RPAD + c * 4);
                float4 xv3 = *(const float4*)(x0 + 3 * RPAD + c * 4);
                float4 wv0 = *(const float4*)(w0 + 0  * RPAD + c * 4);
                float4 wv1 = *(const float4*)(w0 + 8  * RPAD + c * 4);
                float4 wv2 = *(const float4*)(w0 + 16 * RPAD + c * 4);
                float4 wv3 = *(const float4*)(w0 + 24 * RPAD + c * 4);
                #define ACC4(I, XV) \
                    acc[I*4+0] = __fmaf_rn(XV.x, wv0.x, acc[I*4+0]); \
                    acc[I*4+0] = __fmaf_rn(XV.y, wv0.y, acc[I*4+0]); \
                    acc[I*4+0] = __fmaf_rn(XV.z, wv0.z, acc[I*4+0]); \
                    acc[I*4+0] = __fmaf_rn(XV.w, wv0.w, acc[I*4+0]); \
                    acc[I*4+1] = __fmaf_rn(XV.x, wv1.x, acc[I*4+1]); \
                    acc[I*4+1] = __fmaf_rn(XV.y, wv1.y, acc[I*4+1]); \
                    acc[I*4+1] = __fmaf_rn(XV.z, wv1.z, acc[I*4+1]); \
                    acc[I*4+1] = __fmaf_rn(XV.w, wv1.w, acc[I*4+1]); \
                    acc[I*4+2] = __fmaf_rn(XV.x, wv2.x, acc[I*4+2]); \
                    acc[I*4+2] = __fmaf_rn(XV.y, wv2.y, acc[I*4+2]); \
                    acc[I*4+2] = __fmaf_rn(XV.z, wv2.z, acc[I*4+2]); \
                    acc[I*4+2] = __fmaf_rn(XV.w, wv2.w, acc[I*4+2]); \
                    acc[I*4+3] = __fmaf_rn(XV.x, wv3.x, acc[I*4+3]); \
                    acc[I*4+3] = __fmaf_rn(XV.y, wv3.y, acc[I*4+3]); \
                    acc[I*4+3] = __fmaf_rn(XV.z, wv3.z, acc[I*4+3]); \
                    acc[I*4+3] = __fmaf_rn(XV.w, wv3.w, acc[I*4+3]);
                ACC4(0, xv0)
                ACC4(1, xv1)
                ACC4(2, xv2)
                ACC4(3, xv3)
                #undef ACC4
            }

            // Distances + in-lane argmin (k ascending: j then pass; strict <)
            #pragma unroll
            for (int j = 0; j < 4; j++) {
                const int k = kb + lc + 8 * j;
                const float bn = sb[k];
                #pragma unroll
                for (int i = 0; i < 4; i++) {
                    float dd = __fsub_rn(__fadd_rn(av[i], bn),
                                         __fmul_rn(2.0f, acc[i * 4 + j]));
                    if (dd < bd[i]) { bd[i] = dd; bk[i] = k; }
                }
            }
        }

        // ---- Merge across the 8 lc-lanes (tie -> smaller k) --------------
        #pragma unroll
        for (int m = 1; m <= 4; m <<= 1) {
            #pragma unroll
            for (int i = 0; i < 4; i++) {
                float od = __shfl_xor_sync(0xffffffffu, bd[i], m);
                int   ok = __shfl_xor_sync(0xffffffffu, bk[i], m);
                if (od < bd[i] || (od == bd[i] && ok < bk[i])) {
                    bd[i] = od; bk[i] = ok;
                }
            }
        }
        if (lc == 0) {
            #pragma unroll
            for (int i = 0; i < 4; i++) winw[lr * 4 + i] = bk[i];
        }
        __syncwarp();

        // ---- Epilogue: q_out (straight-through), one-hot, loss -----------
        #pragma unroll 4
        for (int it = 0; it < 32; it++) {
            int idx = lane + 32 * it;
            int r = idx & 15, d = idx >> 4;
            int n = row0 + r, b = n >> 10, hw = n & 1023;
            int bi = winw[r];
            float xv   = sxw[r * RPAD + d];
            float diff = __fsub_rn(sw[bi * RPAD + d], xv);
            qout[(size_t)b * 65536 + hw + (size_t)d * 1024] =
                __fadd_rn(xv, diff);
            ls += (double)__fmul_rn(diff, diff);
        }
        if (lane < 16)
            enc[(size_t)(row0 + lane) * KCODES + winw[lane]] = 1.0f;
        __syncwarp();   // winw/sxw safe before next tile's staging
    }

    // ---- Deterministic block-level loss reduction (fixed tree) -------------
    __syncthreads();
    sred[tid] = ls;
    __syncthreads();
    for (int s = NTHR / 2; s > 0; s >>= 1) {
        if (tid < s) sred[tid] += sred[tid + s];
        __syncthreads();
    }

    // Last-block final reduce (fence+atomic; deterministic fixed-order sum)
    __shared__ int isLast;
    if (tid == 0) {
        g_partial[bid] = sred[0];
        __threadfence();
        unsigned old = atomicAdd(&g_count, 1u);
        isLast = (old == NBLK - 1u) ? 1 : 0;
    }
    __syncthreads();
    if (isLast) {
        sred[tid] = (tid < NBLK) ? g_partial[tid] : 0.0;
        __syncthreads();
        for (int s = NTHR / 2; s > 0; s >>= 1) {
            if (tid < s) sred[tid] += sred[tid + s];
            __syncthreads();
        }
        if (tid == 0) {
            float m = (float)(sred[0] / (double)QELEMS);
            out[0] = __fadd_rn(m, __fmul_rn(0.25f, m));  // z_q + 0.25*z_e
            g_count = 0;                                 // reset for replay
        }
    }
}

// ---------------------------------------------------------------------------
extern "C" void kernel_launch(void* const* d_in, const int* in_sizes, int n_in,
                              void* d_out, int out_size) {
    const float* x = (const float*)d_in[0];   // [64,64,32,32] fp32
    const float* w = (const float*)d_in[1];   // [512,64] fp32
    float* out  = (float*)d_out;
    float* qout = out + 1;                    // [4194304] (4B-aligned only)
    float* enc  = out + 1 + QELEMS;           // [65536*512] (4B-aligned only)

    cudaFuncSetAttribute(vq_fused, cudaFuncAttributeMaxDynamicSharedMemorySize,
                         SMEM_BYTES);

    vq_fused<<<NBLK, NTHR, SMEM_BYTES>>>(x, w, out, qout, enc);
}